// round 6
// baseline (speedup 1.0000x reference)
#include <cuda_runtime.h>

// COOTensorProduct: out[b, r] = sum_{c} outer(in1,in2)[b,c] * cb[r,c]
// CG block structure: each output row r = (l3, l1, l2, u, v, m3) reads only
// the (2l1+1)x(2l2+1) column block; all 16 (u,v) pairs of a (l1,l2,l3) group
// share one Wigner block W, gathered at runtime from cb's (u=0,v=0) block.
//
// R6: one block handles ALL l3 of its (l1,l2) pair -> inputs staged and
// a1/a2 registers loaded once; l3 loop pipelines epilogue(l3) with W-gather
// of l3+1. 16 pairs total, split into small (l<=2) / big (contains 3)
// kernels by register class; the two launches overlap on the GPU.

#define CB_W 4096
#define OUT_W 4096

struct Pair { int o1, o2; int gbase[7]; };  // gbase[i] for l3 = |l1-l2| + i

// Layout constants validated by the R1 runtime-scan kernel (pass, 6e-8).
__constant__ Pair SP[9] = {
    /*(0,0)*/ { 0,  0, {   0, 0, 0, 0, 0, 0, 0}},
    /*(0,1)*/ { 0,  4, {  64, 0, 0, 0, 0, 0, 0}},
    /*(0,2)*/ { 0, 16, { 496, 0, 0, 0, 0, 0, 0}},
    /*(1,0)*/ { 4,  0, { 112, 0, 0, 0, 0, 0, 0}},
    /*(1,1)*/ { 4,  4, {  16, 160, 576, 0, 0, 0, 0}},
    /*(1,2)*/ { 4, 16, { 208, 656, 1488, 0, 0, 0, 0}},
    /*(2,0)*/ {16,  0, { 816, 0, 0, 0, 0, 0, 0}},
    /*(2,1)*/ {16,  4, { 256, 896, 1712, 0, 0, 0, 0}},
    /*(2,2)*/ {16, 16, {  32, 304, 976, 1824, 2640, 0, 0}}
};
__constant__ Pair BP[7] = {
    /*(0,3)*/ { 0, 36, {1376, 0, 0, 0, 0, 0, 0}},
    /*(1,3)*/ { 4, 36, { 736, 1600, 2496, 0, 0, 0, 0}},
    /*(2,3)*/ {16, 36, { 352, 1056, 1936, 2784, 3360, 0, 0}},
    /*(3,0)*/ {36,  0, {2048, 0, 0, 0, 0, 0, 0}},
    /*(3,1)*/ {36,  4, {1136, 2160, 2928, 0, 0, 0, 0}},
    /*(3,2)*/ {36, 16, { 400, 1216, 2272, 3072, 3536, 0, 0}},
    /*(3,3)*/ {36, 36, {  48, 448, 1296, 2384, 3216, 3712, 3888}}
};

// ---------------------------------------------------------------------------
// Block = 32 batch lanes x one (l1,l2) pair. v-split: warp w owns
// multiplicity column v=w (perfect warp balance for any l3n). W K2P-padded
// in smem, read via LDS.128 broadcast. sout unions with the sa staging
// buffer (plane-k layout, pad 33 -> conflict-free STS/LDS).
// ---------------------------------------------------------------------------
template <int L1, int L2>
__device__ __forceinline__ void run_pair(
    const Pair pr,
    const float* __restrict__ in1, const float* __restrict__ in2,
    const float* __restrict__ cb,
    float* __restrict__ out, int b0,
    float* sa, float* swp)
{
    constexpr int K1 = 2 * L1 + 1, K2 = 2 * L2 + 1;
    constexpr int C1 = 4 * K1, C2 = 4 * K2;
    constexpr int Q1 = C1 / 4, Q2 = C2 / 4;
    constexpr int K2P = (K2 == 1) ? 1 : ((K2 + 3) & ~3);   // 1,4,8
    constexpr int WROW = K1 * K2P;
    constexpr int LO  = (L1 > L2) ? (L1 - L2) : (L2 - L1);
    constexpr int NL3 = 2 * ((L1 < L2) ? L1 : L2) + 1;     // # of l3 values

    float* sa1  = sa;            // [C1*32]
    float* sa2  = sa + C1 * 32;  // [C2*32]
    float* sout = sa;            // union: alive after registers loaded

    const int tid  = threadIdx.x;
    const int lane = tid & 31;
    const int warp = tid >> 5;   // = v

    // ---- stage inputs via float4 (o1/o2 are multiples of 4) ----
    {
        const float4* p1 = reinterpret_cast<const float4*>(in1) + (size_t)b0 * 16 + (pr.o1 >> 2);
        for (int x = tid; x < 32 * Q1; x += 128) {
            int b = x / Q1, q = x - b * Q1;              // compile-time divisor
            float4 v = p1[(size_t)b * 16 + q];
            sa1[(4 * q + 0) * 32 + b] = v.x;
            sa1[(4 * q + 1) * 32 + b] = v.y;
            sa1[(4 * q + 2) * 32 + b] = v.z;
            sa1[(4 * q + 3) * 32 + b] = v.w;
        }
        const float4* p2 = reinterpret_cast<const float4*>(in2) + (size_t)b0 * 16 + (pr.o2 >> 2);
        for (int x = tid; x < 32 * Q2; x += 128) {
            int b = x / Q2, q = x - b * Q2;
            float4 v = p2[(size_t)b * 16 + q];
            sa2[(4 * q + 0) * 32 + b] = v.x;
            sa2[(4 * q + 1) * 32 + b] = v.y;
            sa2[(4 * q + 2) * 32 + b] = v.z;
            sa2[(4 * q + 3) * 32 + b] = v.w;
        }
    }
    // ---- gather W for first l3 (padded rows, zeros in the pad) ----
    {
        const int l3n0 = 2 * LO + 1;
        const float* wsrc = cb + (size_t)pr.gbase[0] * CB_W + pr.o1 * 64 + pr.o2;
        for (int i = tid; i < l3n0 * WROW; i += 128) {
            int m3 = i / WROW;                           // compile-time divisor
            int r  = i - m3 * WROW;
            int m1 = r / K2P;
            int m2 = r - m1 * K2P;
            swp[i] = (m2 < K2) ? wsrc[(size_t)m3 * CB_W + m1 * 64 + m2] : 0.f;
        }
    }
    __syncthreads();

    // ---- registers: full a1 (4 u-blocks), only this warp's v-block of a2 ----
    float a1[C1];
#pragma unroll
    for (int c = 0; c < C1; c++) a1[c] = sa1[c * 32 + lane];
    float a2p[K2P];
#pragma unroll
    for (int j = 0; j < K2P; j++)
        a2p[j] = (j < K2) ? sa2[(warp * K2 + j) * 32 + lane] : 0.f;
    __syncthreads();   // sa dead -> sout (union) alive

    // ---- l3 loop: compute | sync | (epilogue + gather next W) | sync ----
#pragma unroll 1
    for (int i3 = 0; i3 < NL3; i3++) {
        const int l3n   = 2 * (LO + i3) + 1;
        const int span4 = 4 * l3n;
        const int gbase = pr.gbase[i3];

        for (int m3 = 0; m3 < l3n; m3++) {
            const float* wr = swp + m3 * WROW;
            float acc0 = 0.f, acc1 = 0.f, acc2 = 0.f, acc3 = 0.f;
#pragma unroll
            for (int m1 = 0; m1 < K1; m1++) {
                float s = 0.f;
                if constexpr (K2P % 4 == 0) {
#pragma unroll
                    for (int q = 0; q < K2P / 4; q++) {
                        float4 w4 = *reinterpret_cast<const float4*>(wr + m1 * K2P + 4 * q);
                        s += w4.x * a2p[4 * q + 0];
                        s += w4.y * a2p[4 * q + 1];
                        s += w4.z * a2p[4 * q + 2];
                        s += w4.w * a2p[4 * q + 3];
                    }
                } else {
                    s = wr[m1] * a2p[0];
                }
                acc0 += a1[0 * K1 + m1] * s;
                acc1 += a1[1 * K1 + m1] * s;
                acc2 += a1[2 * K1 + m1] * s;
                acc3 += a1[3 * K1 + m1] * s;
            }
            // rows r = (u*4 + v)*l3n + m3; plane-k staging
            int r, r4, k;
            r = (0 * 4 + warp) * l3n + m3; r4 = r >> 2; k = r & 3;
            sout[(k * span4 + r4) * 33 + lane] = acc0;
            r = (1 * 4 + warp) * l3n + m3; r4 = r >> 2; k = r & 3;
            sout[(k * span4 + r4) * 33 + lane] = acc1;
            r = (2 * 4 + warp) * l3n + m3; r4 = r >> 2; k = r & 3;
            sout[(k * span4 + r4) * 33 + lane] = acc2;
            r = (3 * 4 + warp) * l3n + m3; r4 = r >> 2; k = r & 3;
            sout[(k * span4 + r4) * 33 + lane] = acc3;
        }
        __syncthreads();

        // ---- epilogue(l3): flat, near-division-free, coalesced float4 ----
        {
            const int total = 32 * span4;
            int b  = tid / span4;               // one runtime division
            int r4 = tid - b * span4;
            const int db = 128 / span4;         // block-uniform
            const int dr = 128 - db * span4;
            for (int i = tid; i < total; i += 128) {
                float4 v;
                v.x = sout[(0 * span4 + r4) * 33 + b];
                v.y = sout[(1 * span4 + r4) * 33 + b];
                v.z = sout[(2 * span4 + r4) * 33 + b];
                v.w = sout[(3 * span4 + r4) * 33 + b];
                *reinterpret_cast<float4*>(
                    out + (size_t)(b0 + b) * OUT_W + gbase + 4 * r4) = v;
                b += db; r4 += dr;
                if (r4 >= span4) { r4 -= span4; b++; }
            }
        }
        // ---- gather W for next l3 (disjoint buffer -> same phase) ----
        if (i3 + 1 < NL3) {
            const int l3n1 = l3n + 2;
            const float* wsrc = cb + (size_t)pr.gbase[i3 + 1] * CB_W + pr.o1 * 64 + pr.o2;
            for (int i = tid; i < l3n1 * WROW; i += 128) {
                int m3 = i / WROW;
                int r  = i - m3 * WROW;
                int m1 = r / K2P;
                int m2 = r - m1 * K2P;
                swp[i] = (m2 < K2) ? wsrc[(size_t)m3 * CB_W + m1 * 64 + m2] : 0.f;
            }
        }
        __syncthreads();
    }
}

// ---------------------------------------------------------------------------
__global__ void __launch_bounds__(128, 8)
tp_small(const float* __restrict__ in1, const float* __restrict__ in2,
         const float* __restrict__ cb, float* __restrict__ out)
{
    __shared__ float swp[360];         // max single-l3 W: 9*5*8 (2,2,l3=4)
    __shared__ float ubuf[4752];       // max(sa 40*32, sout 144*33)

    const Pair pr = SP[blockIdx.y];
    const int b0 = blockIdx.x * 32;

#define RP(A, B2) run_pair<A, B2>(pr, in1, in2, cb, out, b0, ubuf, swp)
    switch (blockIdx.y) {
        case 0: RP(0, 0); break;
        case 1: RP(0, 1); break;
        case 2: RP(0, 2); break;
        case 3: RP(1, 0); break;
        case 4: RP(1, 1); break;
        case 5: RP(1, 2); break;
        case 6: RP(2, 0); break;
        case 7: RP(2, 1); break;
        case 8: RP(2, 2); break;
    }
#undef RP
}

__global__ void __launch_bounds__(128, 7)
tp_big(const float* __restrict__ in1, const float* __restrict__ in2,
       const float* __restrict__ cb, float* __restrict__ out)
{
    __shared__ float swp[728];         // max single-l3 W: 13*7*8 (3,3,l3=6)
    __shared__ float ubuf[6864];       // max(sa 56*32, sout 208*33)

    const Pair pr = BP[blockIdx.y];
    const int b0 = blockIdx.x * 32;

#define RP(A, B2) run_pair<A, B2>(pr, in1, in2, cb, out, b0, ubuf, swp)
    switch (blockIdx.y) {
        case 0: RP(0, 3); break;
        case 1: RP(1, 3); break;
        case 2: RP(2, 3); break;
        case 3: RP(3, 0); break;
        case 4: RP(3, 1); break;
        case 5: RP(3, 2); break;
        case 6: RP(3, 3); break;
    }
#undef RP
}

// ---------------------------------------------------------------------------
extern "C" void kernel_launch(void* const* d_in, const int* in_sizes, int n_in,
                              void* d_out, int out_size)
{
    const float* in1 = (const float*)d_in[0];
    const float* in2 = (const float*)d_in[1];
    const float* cb  = (const float*)d_in[2];
    float* out = (float*)d_out;

    int B = in_sizes[0] / 64;

    // Big first: its long (3,3) blocks start in wave 1; small backfills.
    dim3 grid_big(B / 32, 7);
    tp_big<<<grid_big, 128>>>(in1, in2, cb, out);
    dim3 grid_small(B / 32, 9);
    tp_small<<<grid_small, 128>>>(in1, in2, cb, out);
}

// round 7
// speedup vs baseline: 1.2340x; 1.2340x over previous
#include <cuda_runtime.h>

// COOTensorProduct: out[b, r] = sum_{c} outer(in1,in2)[b,c] * cb[r,c]
// CG block structure: each output row r = (l3, l1, l2, u, v, m3) reads only
// the (2l1+1)x(2l2+1) column block; all 16 (u,v) pairs of a (l1,l2,l3) group
// share one Wigner block W, gathered at runtime from cb's (u=0,v=0) block.
//
// R7 = R5 kernels (best: 42.0us) + TRUE concurrency: tp_big / tp_small are
// launched on two streams via the fork-join capture pattern, so the two
// stall-bound kernels (issue ~48% each) interleave on the SMs instead of
// running back-to-back.

#define CB_W 4096
#define OUT_W 4096

struct Group { int l1, l2, l3, gbase, o1, o2; };

// Layout validated by the R1 runtime-scan kernel (pass, rel_err 6e-8).
// First 19 entries: "small" groups (l1<=2 && l2<=2); last 25: "big".
#define N_SMALL 19
#define N_BIG   25
__constant__ Group G[44] = {
    // ---- small (l1<=2, l2<=2) ----
    {0,0,0,   0, 0, 0},{1,1,0,  16, 4, 4},{2,2,0,  32,16,16},
    {0,1,1,  64, 0, 4},{1,0,1, 112, 4, 0},{1,1,1, 160, 4, 4},
    {1,2,1, 208, 4,16},{2,1,1, 256,16, 4},{2,2,1, 304,16,16},
    {0,2,2, 496, 0,16},{1,1,2, 576, 4, 4},{1,2,2, 656, 4,16},
    {2,0,2, 816,16, 0},{2,1,2, 896,16, 4},{2,2,2, 976,16,16},
    {1,2,3,1488, 4,16},{2,1,3,1712,16, 4},{2,2,3,1824,16,16},
    {2,2,4,2640,16,16},
    // ---- big (l1==3 || l2==3) ----
    {3,3,0,  48,36,36},{2,3,1, 352,16,36},{3,2,1, 400,36,16},
    {3,3,1, 448,36,36},{1,3,2, 736, 4,36},{2,3,2,1056,16,36},
    {3,1,2,1136,36, 4},{3,2,2,1216,36,16},{3,3,2,1296,36,36},
    {0,3,3,1376, 0,36},{1,3,3,1600, 4,36},{2,3,3,1936,16,36},
    {3,0,3,2048,36, 0},{3,1,3,2160,36, 4},{3,2,3,2272,36,16},
    {3,3,3,2384,36,36},{1,3,4,2496, 4,36},{2,3,4,2784,16,36},
    {3,1,4,2928,36, 4},{3,2,4,3072,36,16},{3,3,4,3216,36,36},
    {2,3,5,3360,16,36},{3,2,5,3536,36,16},{3,3,5,3712,36,36},
    {3,3,6,3888,36,36}
};

// ---------------------------------------------------------------------------
// Block = 32 batch lanes x one group. v-split: warp w owns multiplicity
// column v=w and loops over ALL m3 rows -> perfect warp balance for any l3n.
// W stored K2P-padded in smem, read via LDS.128 (uniform broadcast).
// sout (plane-k layout, pad 33) is UNIONed with the sa staging buffer.
// ---------------------------------------------------------------------------
template <int L1, int L2>
__device__ __forceinline__ void run_group(
    const Group gr,
    const float* __restrict__ in1, const float* __restrict__ in2,
    const float* __restrict__ cb,
    float* __restrict__ out, int b0,
    float* sa, float* swp)
{
    constexpr int K1 = 2 * L1 + 1, K2 = 2 * L2 + 1;
    constexpr int C1 = 4 * K1, C2 = 4 * K2;
    constexpr int Q1 = C1 / 4, Q2 = C2 / 4;
    constexpr int K2P = (K2 == 1) ? 1 : ((K2 + 3) & ~3);   // 1,4,8
    constexpr int WROW = K1 * K2P;

    float* sa1  = sa;            // [C1*32]
    float* sa2  = sa + C1 * 32;  // [C2*32]
    float* sout = sa;            // union: alive after registers loaded

    const int tid  = threadIdx.x;
    const int lane = tid & 31;
    const int warp = tid >> 5;   // = v
    const int l3n  = 2 * gr.l3 + 1;

    // ---- stage inputs via float4 (o1/o2 are multiples of 4) ----
    {
        const float4* p1 = reinterpret_cast<const float4*>(in1) + (size_t)b0 * 16 + (gr.o1 >> 2);
        for (int x = tid; x < 32 * Q1; x += 128) {
            int b = x / Q1, q = x - b * Q1;              // compile-time divisor
            float4 v = p1[(size_t)b * 16 + q];
            sa1[(4 * q + 0) * 32 + b] = v.x;
            sa1[(4 * q + 1) * 32 + b] = v.y;
            sa1[(4 * q + 2) * 32 + b] = v.z;
            sa1[(4 * q + 3) * 32 + b] = v.w;
        }
        const float4* p2 = reinterpret_cast<const float4*>(in2) + (size_t)b0 * 16 + (gr.o2 >> 2);
        for (int x = tid; x < 32 * Q2; x += 128) {
            int b = x / Q2, q = x - b * Q2;
            float4 v = p2[(size_t)b * 16 + q];
            sa2[(4 * q + 0) * 32 + b] = v.x;
            sa2[(4 * q + 1) * 32 + b] = v.y;
            sa2[(4 * q + 2) * 32 + b] = v.z;
            sa2[(4 * q + 3) * 32 + b] = v.w;
        }
    }
    // ---- padded Wigner gather from cb (u=0,v=0 block); zeros in the pad ----
    for (int i = tid; i < l3n * WROW; i += 128) {
        int m3 = i / WROW;                               // compile-time divisor
        int r  = i - m3 * WROW;
        int m1 = r / K2P;
        int m2 = r - m1 * K2P;
        float wv = 0.f;
        if (m2 < K2)
            wv = cb[(size_t)(gr.gbase + m3) * CB_W + (gr.o1 + m1) * 64 + gr.o2 + m2];
        swp[i] = wv;
    }
    __syncthreads();

    // ---- registers: full a1 (4 u-blocks), only this warp's v-block of a2 ----
    float a1[C1];
#pragma unroll
    for (int c = 0; c < C1; c++) a1[c] = sa1[c * 32 + lane];
    float a2p[K2P];
#pragma unroll
    for (int j = 0; j < K2P; j++)
        a2p[j] = (j < K2) ? sa2[(warp * K2 + j) * 32 + lane] : 0.f;
    __syncthreads();   // sa dead -> sout (union) alive

    const int span4 = 4 * l3n;

    for (int m3 = 0; m3 < l3n; m3++) {
        const float* wr = swp + m3 * WROW;
        float acc0 = 0.f, acc1 = 0.f, acc2 = 0.f, acc3 = 0.f;
#pragma unroll
        for (int m1 = 0; m1 < K1; m1++) {
            float s = 0.f;
            if constexpr (K2P % 4 == 0) {
#pragma unroll
                for (int q = 0; q < K2P / 4; q++) {
                    float4 w4 = *reinterpret_cast<const float4*>(wr + m1 * K2P + 4 * q);
                    s += w4.x * a2p[4 * q + 0];
                    s += w4.y * a2p[4 * q + 1];
                    s += w4.z * a2p[4 * q + 2];
                    s += w4.w * a2p[4 * q + 3];
                }
            } else {
                s = wr[m1] * a2p[0];
            }
            acc0 += a1[0 * K1 + m1] * s;
            acc1 += a1[1 * K1 + m1] * s;
            acc2 += a1[2 * K1 + m1] * s;
            acc3 += a1[3 * K1 + m1] * s;
        }
        // rows r = (u*4 + v)*l3n + m3; plane-k staging (conflict-free STS)
        {
            int r, r4, k;
            r = (0 * 4 + warp) * l3n + m3; r4 = r >> 2; k = r & 3;
            sout[(k * span4 + r4) * 33 + lane] = acc0;
            r = (1 * 4 + warp) * l3n + m3; r4 = r >> 2; k = r & 3;
            sout[(k * span4 + r4) * 33 + lane] = acc1;
            r = (2 * 4 + warp) * l3n + m3; r4 = r >> 2; k = r & 3;
            sout[(k * span4 + r4) * 33 + lane] = acc2;
            r = (3 * 4 + warp) * l3n + m3; r4 = r >> 2; k = r & 3;
            sout[(k * span4 + r4) * 33 + lane] = acc3;
        }
    }
    __syncthreads();

    // ---- flat, near-division-free coalesced epilogue ----
    {
        const int total = 32 * span4;
        int b  = tid / span4;               // single runtime division
        int r4 = tid - b * span4;
        const int db = 128 / span4;         // block-uniform
        const int dr = 128 - db * span4;
        for (int i = tid; i < total; i += 128) {
            float4 v;
            v.x = sout[(0 * span4 + r4) * 33 + b];
            v.y = sout[(1 * span4 + r4) * 33 + b];
            v.z = sout[(2 * span4 + r4) * 33 + b];
            v.w = sout[(3 * span4 + r4) * 33 + b];
            *reinterpret_cast<float4*>(
                out + (size_t)(b0 + b) * OUT_W + gr.gbase + 4 * r4) = v;
            b += db; r4 += dr;
            if (r4 >= span4) { r4 -= span4; b++; }
        }
    }
}

// ---------------------------------------------------------------------------
__global__ void __launch_bounds__(128, 8)
tp_small(const float* __restrict__ in1, const float* __restrict__ in2,
         const float* __restrict__ cb, float* __restrict__ out)
{
    __shared__ float swp[360];         // max l3n*K1*K2P = 9*5*8 (2,2,4)
    __shared__ float ubuf[4752];       // max(sa 40*32, sout 144*33)

    const Group gr = G[blockIdx.y];
    const int b0 = blockIdx.x * 32;

#define RG(A, B2) run_group<A, B2>(gr, in1, in2, cb, out, b0, ubuf, swp)
    switch (gr.l1 * 3 + gr.l2) {
        case 0: RG(0, 0); break;
        case 1: RG(0, 1); break;
        case 2: RG(0, 2); break;
        case 3: RG(1, 0); break;
        case 4: RG(1, 1); break;
        case 5: RG(1, 2); break;
        case 6: RG(2, 0); break;
        case 7: RG(2, 1); break;
        case 8: RG(2, 2); break;
    }
#undef RG
}

__global__ void __launch_bounds__(128, 7)
tp_big(const float* __restrict__ in1, const float* __restrict__ in2,
       const float* __restrict__ cb, float* __restrict__ out)
{
    __shared__ float swp[728];         // max l3n*K1*K2P = 13*7*8 (3,3,6)
    __shared__ float ubuf[6864];       // max(sa 56*32, sout 208*33)

    const Group gr = G[N_SMALL + blockIdx.y];
    const int b0 = blockIdx.x * 32;

#define RG(A, B2) run_group<A, B2>(gr, in1, in2, cb, out, b0, ubuf, swp)
    switch (gr.l1 * 4 + gr.l2) {
        case  3: RG(0, 3); break;
        case  7: RG(1, 3); break;
        case 11: RG(2, 3); break;
        case 12: RG(3, 0); break;
        case 13: RG(3, 1); break;
        case 14: RG(3, 2); break;
        case 15: RG(3, 3); break;
    }
#undef RG
}

// ---------------------------------------------------------------------------
// Fork-join launch: tp_big on the origin stream, tp_small on a forked
// stream, joined back. Under graph capture this produces two PARALLEL
// branches (no dependency edge), so the kernels run concurrently.
// No device memory is allocated (streams/events are host objects).
// ---------------------------------------------------------------------------
extern "C" void kernel_launch(void* const* d_in, const int* in_sizes, int n_in,
                              void* d_out, int out_size)
{
    const float* in1 = (const float*)d_in[0];
    const float* in2 = (const float*)d_in[1];
    const float* cb  = (const float*)d_in[2];
    float* out = (float*)d_out;

    int B = in_sizes[0] / 64;

    cudaStream_t s2;
    cudaStreamCreateWithFlags(&s2, cudaStreamNonBlocking);
    cudaEvent_t eFork, eJoin;
    cudaEventCreateWithFlags(&eFork, cudaEventDisableTiming);
    cudaEventCreateWithFlags(&eJoin, cudaEventDisableTiming);

    // fork: s2 depends on everything before this point on the origin stream
    cudaEventRecord(eFork, 0);
    cudaStreamWaitEvent(s2, eFork, 0);

    dim3 grid_big(B / 32, N_BIG);
    tp_big<<<grid_big, 128, 0, 0>>>(in1, in2, cb, out);
    dim3 grid_small(B / 32, N_SMALL);
    tp_small<<<grid_small, 128, 0, s2>>>(in1, in2, cb, out);

    // join: origin stream waits for the s2 branch
    cudaEventRecord(eJoin, s2);
    cudaStreamWaitEvent(0, eJoin, 0);

    cudaEventDestroy(eFork);
    cudaEventDestroy(eJoin);
    cudaStreamDestroy(s2);
}